// round 4
// baseline (speedup 1.0000x reference)
#include <cuda_runtime.h>
#include <cuda_fp16.h>
#include <cstdint>

// ============================================================================
// Problem constants (fixed shapes for SVMModel_19267223290147)
// ============================================================================
#define BB 2048      // batch rows
#define NN 32768     // train rows
#define DD 128       // feature dim
#define BT 128       // CTA B-tile (M)
#define NT 128       // CTA N-tile
#define NSPLITS 8    // N chunks across grid (ns = bx & 7)
#define BTILES  16   // B tiles across grid (bt = bx >> 3)
#define NCHUNK (NN / NSPLITS)       // 4096
#define TILES  (NCHUNK / NT)        // 32
#define TPREP  (NCHUNK / BTILES)    // 256 t-rows converted per CTA
#define THREADS 256
#define NBUF 3

// SMEM: A tile (32KB) + 3-deep B ring (96KB). Tiles stored as 2 chunks of
// [128 rows x 64 fp16 (128B)] SW128-swizzled.
#define SMEM_A 0
#define SMEM_B 32768
#define TILE_BYTES 32768
#define SMEM_TOTAL (SMEM_B + NBUF * TILE_BYTES)

#define SWZ(o) ((o) ^ (((o) >> 3) & 0x70))

// ============================================================================
// Device globals (static allocation: allowed)
// ============================================================================
__device__ __half g_tbf[NN * DD];              // train_data fp16
__device__ float  g_c1[NN];                    // W[n] * exp(-g*t2[n])
__device__ float  g_partial[NSPLITS * BB * 2];
__device__ unsigned          g_cnt[NSPLITS];   // per-ns barrier counters (0-init)
__device__ volatile unsigned g_sns[NSPLITS];   // per-ns barrier sense
__device__ unsigned          g_arr[BTILES];    // per-btile arrival counters (0-init)

// ============================================================================
// PTX helpers (sm_100 base-target safe)
// ============================================================================
__device__ __forceinline__ uint32_t smem_u32(const void* p) {
    uint32_t a;
    asm("{ .reg .u64 t; cvta.to.shared.u64 t, %1; cvt.u32.u64 %0, t; }" : "=r"(a) : "l"(p));
    return a;
}
__device__ __forceinline__ float ex2f(float x) {
    float y; asm("ex2.approx.f32 %0, %1;" : "=f"(y) : "f"(x)); return y;
}
__device__ __forceinline__ void cp_async16(uint32_t dst, const void* src) {
    asm volatile("cp.async.cg.shared.global [%0], [%1], 16;" :: "r"(dst), "l"(src));
}
#define CP_COMMIT() asm volatile("cp.async.commit_group;" ::: "memory")

__device__ __forceinline__ void ldsm4(uint32_t* r, uint32_t addr) {
    asm volatile("ldmatrix.sync.aligned.m8n8.x4.shared.b16 {%0,%1,%2,%3}, [%4];"
                 : "=r"(r[0]), "=r"(r[1]), "=r"(r[2]), "=r"(r[3]) : "r"(addr));
}
__device__ __forceinline__ void mma16816(float* c, const uint32_t* a, const uint32_t* b) {
    asm volatile(
        "mma.sync.aligned.m16n8k16.row.col.f32.f16.f16.f32 "
        "{%0,%1,%2,%3}, {%4,%5,%6,%7}, {%8,%9}, {%0,%1,%2,%3};"
        : "+f"(c[0]), "+f"(c[1]), "+f"(c[2]), "+f"(c[3])
        : "r"(a[0]), "r"(a[1]), "r"(a[2]), "r"(a[3]), "r"(b[0]), "r"(b[1]));
}

// cp.async one [128 x 128 fp16] tile into SMEM ring slot (chunked SW128).
__device__ __forceinline__ void issue_tile(uint32_t sm_base, const __half* src) {
    int tid = threadIdx.x;
    #pragma unroll
    for (int it = 0; it < 8; it++) {
        int k = tid + it * 256;
        int row = k >> 4;
        int rem = k & 15;
        int c = rem >> 3;
        int j = rem & 7;
        uint32_t dst = sm_base + c * 16384 + SWZ((uint32_t)(row * 128 + j * 16));
        cp_async16(dst, src + row * 128 + c * 64 + j * 8);
    }
}

// ============================================================================
// Fused persistent kernel: prep -> per-ns barrier -> GEMM+exp2 -> fused reduce
// ============================================================================
__global__ void __launch_bounds__(THREADS, 1)
rbf_fused_kernel(const float* __restrict__ x, const float* __restrict__ train,
                 const float* __restrict__ gamma, const float* __restrict__ W,
                 const float* __restrict__ bias, float* __restrict__ out) {
    extern __shared__ char smem[];
    __shared__ float ex_s[BT];
    __shared__ int   s_flag;
    uint32_t sb = smem_u32(smem);
    int tid = threadIdx.x;
    int lane = tid & 31;
    int wid = tid >> 5;
    int warp_m = wid & 3;     // 4 warps along M (32 rows each)
    int warp_n = wid >> 2;    // 2 warps along N (64 cols each)
    int g  = lane >> 2;
    int tg = lane & 3;

    int bx = blockIdx.x;
    int ns = bx & (NSPLITS - 1);
    int bt = bx >> 3;
    int m0 = bt * BT;
    int n_base = ns * NCHUNK;

    float gm = __ldg(gamma);
    float sc = 2.0f * gm * 1.4426950408889634f;   // 2*gamma*log2(e)

    // ---- Phase A1: x-prep directly into SMEM A (scaled fp16, SW128) ----
    // warp handles row (wid + 8*it); lane covers 4 cols.
    {
        int chunk = lane >> 4;
        int cbyte = 8 * lane - 128 * chunk;   // byte offset within chunk row
        #pragma unroll 4
        for (int it = 0; it < 16; it++) {
            int r = wid + it * 8;
            float4 v = reinterpret_cast<const float4*>(x + (size_t)(m0 + r) * DD)[lane];
            float ss = v.x * v.x + v.y * v.y + v.z * v.z + v.w * v.w;
            #pragma unroll
            for (int o = 16; o > 0; o >>= 1) ss += __shfl_xor_sync(0xFFFFFFFFu, ss, o);
            char* p = smem + SMEM_A + chunk * 16384 + SWZ((uint32_t)(r * 128 + cbyte));
            *reinterpret_cast<__half2*>(p)     = __floats2half2_rn(v.x * sc, v.y * sc);
            *reinterpret_cast<__half2*>(p + 4) = __floats2half2_rn(v.z * sc, v.w * sc);
            if (lane == 0) ex_s[r] = expf(-gm * ss);
        }
    }
    __syncthreads();

    // ---- Hoist A fragments (constant for whole kernel) ----
    int a_row_in_warp = ((lane >> 3) & 1) * 8 + (lane & 7);
    int a_kb16 = ((lane >> 4) & 1) * 16;
    int b_row_in_nb = lane & 7;
    int b_kb16 = (lane >> 3) * 16;

    uint32_t af[4][2][2][4];   // [kq][ms][kk][4]
    #pragma unroll
    for (int kq = 0; kq < 4; kq++) {
        int chunk = kq >> 1;
        int kbyte0 = (kq & 1) * 64;
        uint32_t base = sb + SMEM_A + chunk * 16384;
        #pragma unroll
        for (int ms = 0; ms < 2; ms++) {
            int row = warp_m * 32 + ms * 16 + a_row_in_warp;
            ldsm4(af[kq][ms][0], base + SWZ((uint32_t)(row * 128 + kbyte0 + a_kb16)));
            ldsm4(af[kq][ms][1], base + SWZ((uint32_t)(row * 128 + kbyte0 + 32 + a_kb16)));
        }
    }

    // ---- Phase A2: t-prep, 256 rows per CTA into g_tbf / g_c1 ----
    {
        int r0 = n_base + bt * TPREP;
        #pragma unroll 4
        for (int it = 0; it < 32; it++) {
            int r = r0 + wid + it * 8;
            float4 v = reinterpret_cast<const float4*>(train + (size_t)r * DD)[lane];
            float ss = v.x * v.x + v.y * v.y + v.z * v.z + v.w * v.w;
            #pragma unroll
            for (int o = 16; o > 0; o >>= 1) ss += __shfl_xor_sync(0xFFFFFFFFu, ss, o);
            __half2* dst = reinterpret_cast<__half2*>(g_tbf + (size_t)r * DD + lane * 4);
            dst[0] = __floats2half2_rn(v.x, v.y);
            dst[1] = __floats2half2_rn(v.z, v.w);
            if (lane == 0) g_c1[r] = __ldg(W + r) * expf(-gm * ss);
        }
    }

    // ---- Per-ns sense-reversing barrier (16 CTAs share one t-chunk) ----
    __threadfence();
    __syncthreads();
    if (tid == 0) {
        unsigned s = g_sns[ns];
        if (atomicAdd(&g_cnt[ns], 1) == BTILES - 1) {
            g_cnt[ns] = 0;
            __threadfence();
            g_sns[ns] = s ^ 1;
        } else {
            while (g_sns[ns] == s) {}
        }
        __threadfence();
    }
    __syncthreads();

    // ---- Prologue: tiles 0,1 into ring slots 0,1 ----
    issue_tile(sb + SMEM_B + 0 * TILE_BYTES, g_tbf + (size_t)n_base * DD);
    CP_COMMIT();
    issue_tile(sb + SMEM_B + 1 * TILE_BYTES, g_tbf + (size_t)(n_base + NT) * DD);
    CP_COMMIT();

    float racc[2][2] = {{0.f, 0.f}, {0.f, 0.f}};

    // ---- Main loop: one sync per tile, 3-slot ring, pipelined epilogue ----
    for (int i = 0; i < TILES; i++) {
        asm volatile("cp.async.wait_group 1;" ::: "memory");  // tile i resident
        __syncthreads();                                      // visible to all

        // refill slot (i+2)%3 (consumed at i-1; quiescent after the sync)
        if (i + 2 < TILES)
            issue_tile(sb + SMEM_B + ((i + 2) % NBUF) * TILE_BYTES,
                       g_tbf + (size_t)(n_base + (i + 2) * NT) * DD);
        CP_COMMIT();  // empty commit in tail keeps group accounting uniform

        uint32_t Bb = sb + SMEM_B + (i % NBUF) * TILE_BYTES;
        const float* c1base = g_c1 + n_base + i * NT + warp_n * 64;

        float acc[2][2][4];   // [parity][ms][4] — epilogue pipelined one nb behind
        float2 wv[2];

        #pragma unroll
        for (int nb = 0; nb < 8; nb++) {
            int p = nb & 1;
            int row = warp_n * 64 + nb * 8 + b_row_in_nb;
            uint32_t bf[4][4];
            #pragma unroll
            for (int kq = 0; kq < 4; kq++) {
                int chunk = kq >> 1;
                int kbyte0 = (kq & 1) * 64;
                ldsm4(bf[kq], Bb + chunk * 16384 +
                      SWZ((uint32_t)(row * 128 + kbyte0 + b_kb16)));
            }
            wv[p] = *reinterpret_cast<const float2*>(c1base + nb * 8 + 2 * tg);
            #pragma unroll
            for (int ms = 0; ms < 2; ms++)
                #pragma unroll
                for (int c = 0; c < 4; c++) acc[p][ms][c] = 0.f;
            #pragma unroll
            for (int kq = 0; kq < 4; kq++)
                #pragma unroll
                for (int kk = 0; kk < 2; kk++)
                    #pragma unroll
                    for (int ms = 0; ms < 2; ms++)
                        mma16816(acc[p][ms], af[kq][ms][kk], &bf[kq][kk * 2]);

            if (nb > 0) {  // epilogue of nb-1: MUFU overlaps this nb's HMMA
                int q = p ^ 1;
                #pragma unroll
                for (int ms = 0; ms < 2; ms++) {
                    racc[ms][0] = fmaf(ex2f(acc[q][ms][0]), wv[q].x, racc[ms][0]);
                    racc[ms][0] = fmaf(ex2f(acc[q][ms][1]), wv[q].y, racc[ms][0]);
                    racc[ms][1] = fmaf(ex2f(acc[q][ms][2]), wv[q].x, racc[ms][1]);
                    racc[ms][1] = fmaf(ex2f(acc[q][ms][3]), wv[q].y, racc[ms][1]);
                }
            }
        }
        // epilogue of nb=7 (parity 1) — drains under next tile's wait+sync
        #pragma unroll
        for (int ms = 0; ms < 2; ms++) {
            racc[ms][0] = fmaf(ex2f(acc[1][ms][0]), wv[1].x, racc[ms][0]);
            racc[ms][0] = fmaf(ex2f(acc[1][ms][1]), wv[1].y, racc[ms][0]);
            racc[ms][1] = fmaf(ex2f(acc[1][ms][2]), wv[1].x, racc[ms][1]);
            racc[ms][1] = fmaf(ex2f(acc[1][ms][3]), wv[1].y, racc[ms][1]);
        }
    }

    // ---- Partial write (deterministic slots) ----
    #pragma unroll
    for (int ms = 0; ms < 2; ms++)
        #pragma unroll
        for (int h = 0; h < 2; h++) {
            float v = racc[ms][h];
            v += __shfl_xor_sync(0xFFFFFFFFu, v, 1);
            v += __shfl_xor_sync(0xFFFFFFFFu, v, 2);
            if (tg == 0) {
                int b = m0 + warp_m * 32 + ms * 16 + h * 8 + g;
                g_partial[(ns * BB + b) * 2 + warp_n] = v;
            }
        }

    // ---- Fused reduce: last of the 8 CTAs sharing this b-tile finishes it ----
    __threadfence();
    __syncthreads();
    if (tid == 0) s_flag = (atomicAdd(&g_arr[bt], 1) == NSPLITS - 1);
    __syncthreads();
    if (s_flag) {
        __threadfence();
        if (tid < BT) {
            int b = m0 + tid;
            float s = 0.0f;
            #pragma unroll
            for (int n2 = 0; n2 < NSPLITS; n2++) {
                s += g_partial[(n2 * BB + b) * 2 + 0];
                s += g_partial[(n2 * BB + b) * 2 + 1];
            }
            out[b] = fmaf(ex_s[tid], s, __ldg(bias));
        }
        if (tid == 0) g_arr[bt] = 0;   // reset for next graph replay
    }
}

// ============================================================================
// Entry — single fused launch (128 CTAs, all resident: barrier-safe)
// ============================================================================
extern "C" void kernel_launch(void* const* d_in, const int* in_sizes, int n_in,
                              void* d_out, int out_size) {
    const float* x     = (const float*)d_in[0];   // [2048, 128]
    const float* train = (const float*)d_in[1];   // [32768, 128]
    const float* gamma = (const float*)d_in[2];   // [1]
    const float* W     = (const float*)d_in[3];   // [1, 32768]
    const float* bias  = (const float*)d_in[4];   // [1]
    float* out = (float*)d_out;                   // [2048, 1]

    cudaFuncSetAttribute(rbf_fused_kernel,
                         cudaFuncAttributeMaxDynamicSharedMemorySize, SMEM_TOTAL);

    rbf_fused_kernel<<<NSPLITS * BTILES, THREADS, SMEM_TOTAL>>>(
        x, train, gamma, W, bias, out);
}

// round 6
// speedup vs baseline: 1.1071x; 1.1071x over previous
#include <cuda_runtime.h>
#include <cuda_fp16.h>
#include <cstdint>

// ============================================================================
// Problem constants (fixed shapes for SVMModel_19267223290147)
// ============================================================================
#define BB 2048      // batch rows
#define NN 32768     // train rows
#define DD 128       // feature dim
#define BT 128       // CTA B-tile (M)
#define NT 128       // CTA N-tile
#define NSPLITS 8    // N chunks across grid.x
#define BTILES  16   // B tiles across grid.y
#define NCHUNK (NN / NSPLITS)     // 4096
#define TILES  (NCHUNK / NT)      // 32
#define THREADS 256
#define NBUF 3

// SMEM: A tile (32KB) + 3-deep B ring (96KB). Tiles stored as 2 chunks of
// [128 rows x 64 fp16 (128B)] SW128-swizzled.
#define SMEM_A 0
#define SMEM_B 32768
#define TILE_BYTES 32768
#define SMEM_TOTAL (SMEM_B + NBUF * TILE_BYTES)

#define SWZ(o) ((o) ^ (((o) >> 3) & 0x70))

// ============================================================================
// Device globals (static allocation: allowed)
// ============================================================================
__device__ __half g_xbf[BB * DD];              // x * (2*gamma*log2e) fp16
__device__ __half g_tbf[NN * DD];              // train_data fp16
__device__ float  g_c1[NN];                    // W[n] * exp(-g*t2[n])
__device__ float  g_ex[BB];                    // exp(-g*x2[b])
__device__ float  g_partial[NSPLITS * BB * 2];
__device__ unsigned g_arr[BTILES];             // per-btile arrival counters (0-init)

// ============================================================================
// PTX helpers (sm_100 base-target safe)
// ============================================================================
__device__ __forceinline__ uint32_t smem_u32(const void* p) {
    uint32_t a;
    asm("{ .reg .u64 t; cvta.to.shared.u64 t, %1; cvt.u32.u64 %0, t; }" : "=r"(a) : "l"(p));
    return a;
}
__device__ __forceinline__ float ex2f(float x) {
    float y; asm("ex2.approx.f32 %0, %1;" : "=f"(y) : "f"(x)); return y;
}
__device__ __forceinline__ void cp_async16(uint32_t dst, const void* src) {
    asm volatile("cp.async.cg.shared.global [%0], [%1], 16;" :: "r"(dst), "l"(src));
}
#define CP_COMMIT() asm volatile("cp.async.commit_group;" ::: "memory")

__device__ __forceinline__ void ldsm4(uint32_t* r, uint32_t addr) {
    asm volatile("ldmatrix.sync.aligned.m8n8.x4.shared.b16 {%0,%1,%2,%3}, [%4];"
                 : "=r"(r[0]), "=r"(r[1]), "=r"(r[2]), "=r"(r[3]) : "r"(addr));
}
// NON-volatile: pure register op; lets ptxas software-pipeline / interleave.
__device__ __forceinline__ void mma16816(float* c, const uint32_t* a, const uint32_t* b) {
    asm("mma.sync.aligned.m16n8k16.row.col.f32.f16.f16.f32 "
        "{%0,%1,%2,%3}, {%4,%5,%6,%7}, {%8,%9}, {%0,%1,%2,%3};"
        : "+f"(c[0]), "+f"(c[1]), "+f"(c[2]), "+f"(c[3])
        : "r"(a[0]), "r"(a[1]), "r"(a[2]), "r"(a[3]), "r"(b[0]), "r"(b[1]));
}

// cp.async one [128 x 128 fp16] tile into an SMEM ring slot (chunked SW128).
__device__ __forceinline__ void issue_tile(uint32_t sm_base, const __half* src) {
    int tid = threadIdx.x;
    #pragma unroll
    for (int it = 0; it < 8; it++) {
        int k = tid + it * 256;
        int row = k >> 4;
        int rem = k & 15;
        int c = rem >> 3;
        int j = rem & 7;
        uint32_t dst = sm_base + c * 16384 + SWZ((uint32_t)(row * 128 + j * 16));
        cp_async16(dst, src + row * 128 + c * 64 + j * 8);
    }
}

// ============================================================================
// Prep kernels (fp32 norms; x pre-scaled by 2*gamma*log2e)
// ============================================================================
__global__ void prep_x_kernel(const float* __restrict__ x, const float* __restrict__ gamma) {
    int w = (blockIdx.x * blockDim.x + threadIdx.x) >> 5;
    int lane = threadIdx.x & 31;
    if (w >= BB) return;
    float gm = gamma[0];
    float s = 2.0f * gm * 1.4426950408889634f;
    float4 v = reinterpret_cast<const float4*>(x + w * DD)[lane];
    float ss = v.x * v.x + v.y * v.y + v.z * v.z + v.w * v.w;
    #pragma unroll
    for (int o = 16; o > 0; o >>= 1) ss += __shfl_xor_sync(0xFFFFFFFFu, ss, o);
    __half2* dst = reinterpret_cast<__half2*>(g_xbf + w * DD + lane * 4);
    dst[0] = __floats2half2_rn(v.x * s, v.y * s);
    dst[1] = __floats2half2_rn(v.z * s, v.w * s);
    if (lane == 0) g_ex[w] = expf(-gm * ss);
}

__global__ void prep_t_kernel(const float* __restrict__ t, const float* __restrict__ gamma,
                              const float* __restrict__ W) {
    int w = (blockIdx.x * blockDim.x + threadIdx.x) >> 5;
    int lane = threadIdx.x & 31;
    if (w >= NN) return;
    float4 v = reinterpret_cast<const float4*>(t + w * DD)[lane];
    float ss = v.x * v.x + v.y * v.y + v.z * v.z + v.w * v.w;
    #pragma unroll
    for (int o = 16; o > 0; o >>= 1) ss += __shfl_xor_sync(0xFFFFFFFFu, ss, o);
    __half2* dst = reinterpret_cast<__half2*>(g_tbf + w * DD + lane * 4);
    dst[0] = __floats2half2_rn(v.x, v.y);
    dst[1] = __floats2half2_rn(v.z, v.w);
    if (lane == 0) g_c1[w] = W[w] * expf(-gamma[0] * ss);
}

// ============================================================================
// Main kernel: fp16 mma GEMM + exp2 epilogue, 4-nb groups (8 indep MMA chains)
// ============================================================================
__global__ void __launch_bounds__(THREADS, 1)
rbf_main_kernel(const float* __restrict__ bias, float* __restrict__ out) {
    extern __shared__ char smem[];
    __shared__ int s_flag;
    uint32_t sb = smem_u32(smem);
    int tid = threadIdx.x;
    int lane = tid & 31;
    int wid = tid >> 5;
    int warp_m = wid & 3;     // 4 warps along M (32 rows each)
    int warp_n = wid >> 2;    // 2 warps along N (64 cols each)
    int g  = lane >> 2;
    int tg = lane & 3;

    int ns = blockIdx.x;
    int bt = blockIdx.y;
    int m0 = bt * BT;
    int n_base = ns * NCHUNK;

    // Prologue: A tile + B tiles 0,1 into ring slots 0,1
    issue_tile(sb + SMEM_A, g_xbf + (size_t)m0 * DD);
    issue_tile(sb + SMEM_B + 0 * TILE_BYTES, g_tbf + (size_t)n_base * DD);
    CP_COMMIT();
    issue_tile(sb + SMEM_B + 1 * TILE_BYTES, g_tbf + (size_t)(n_base + NT) * DD);
    CP_COMMIT();

    int a_row_in_warp = ((lane >> 3) & 1) * 8 + (lane & 7);
    int a_kb16 = ((lane >> 4) & 1) * 16;
    int b_row_in_nb = lane & 7;
    int b_kb16 = (lane >> 3) * 16;

    asm volatile("cp.async.wait_group 1;" ::: "memory");  // A + B0 resident
    __syncthreads();

    // Hoist A fragments (constant across the whole tile loop): 64 regs
    uint32_t af[4][2][2][4];   // [kq][ms][kk][4]
    #pragma unroll
    for (int kq = 0; kq < 4; kq++) {
        int chunk = kq >> 1;
        int kbyte0 = (kq & 1) * 64;
        uint32_t base = sb + SMEM_A + chunk * 16384;
        #pragma unroll
        for (int ms = 0; ms < 2; ms++) {
            int row = warp_m * 32 + ms * 16 + a_row_in_warp;
            ldsm4(af[kq][ms][0], base + SWZ((uint32_t)(row * 128 + kbyte0 + a_kb16)));
            ldsm4(af[kq][ms][1], base + SWZ((uint32_t)(row * 128 + kbyte0 + 32 + a_kb16)));
        }
    }

    float racc[2][2] = {{0.f, 0.f}, {0.f, 0.f}};

    for (int i = 0; i < TILES; i++) {
        asm volatile("cp.async.wait_group 1;" ::: "memory");  // tile i resident
        __syncthreads();

        // refill slot (i+2)%3 (its previous tile i-1 was consumed before the sync)
        if (i + 2 < TILES)
            issue_tile(sb + SMEM_B + ((i + 2) % NBUF) * TILE_BYTES,
                       g_tbf + (size_t)(n_base + (i + 2) * NT) * DD);
        CP_COMMIT();

        uint32_t Bb = sb + SMEM_B + (i % NBUF) * TILE_BYTES;
        const float* c1base = g_c1 + n_base + i * NT + warp_n * 64;

        // Two groups of 4 nb each. Within a group: loop kq->kk->nb->ms gives
        // 8 independent accumulator chains; dependent MMAs are 8 issues apart.
        #pragma unroll
        for (int h = 0; h < 2; h++) {
            uint32_t bf[4][4][4];   // [nb4][kq][4]  (64 regs)
            #pragma unroll
            for (int nb4 = 0; nb4 < 4; nb4++) {
                int row = warp_n * 64 + (h * 4 + nb4) * 8 + b_row_in_nb;
                #pragma unroll
                for (int kq = 0; kq < 4; kq++) {
                    int chunk = kq >> 1;
                    int kbyte0 = (kq & 1) * 64;
                    ldsm4(bf[nb4][kq], Bb + chunk * 16384 +
                          SWZ((uint32_t)(row * 128 + kbyte0 + b_kb16)));
                }
            }
            float acc[4][2][4];     // [nb4][ms][4]  (32 regs)
            #pragma unroll
            for (int nb4 = 0; nb4 < 4; nb4++)
                #pragma unroll
                for (int ms = 0; ms < 2; ms++)
                    #pragma unroll
                    for (int c = 0; c < 4; c++) acc[nb4][ms][c] = 0.f;

            #pragma unroll
            for (int kq = 0; kq < 4; kq++)
                #pragma unroll
                for (int kk = 0; kk < 2; kk++)
                    #pragma unroll
                    for (int nb4 = 0; nb4 < 4; nb4++)
                        #pragma unroll
                        for (int ms = 0; ms < 2; ms++)
                            mma16816(acc[nb4][ms], af[kq][ms][kk], &bf[nb4][kq][kk * 2]);

            // Epilogue for this group (ex2 + fma; overlaps next group's MMAs)
            #pragma unroll
            for (int nb4 = 0; nb4 < 4; nb4++) {
                float2 w = *reinterpret_cast<const float2*>(
                    c1base + (h * 4 + nb4) * 8 + 2 * tg);
                #pragma unroll
                for (int ms = 0; ms < 2; ms++) {
                    racc[ms][0] = fmaf(ex2f(acc[nb4][ms][0]), w.x, racc[ms][0]);
                    racc[ms][0] = fmaf(ex2f(acc[nb4][ms][1]), w.y, racc[ms][0]);
                    racc[ms][1] = fmaf(ex2f(acc[nb4][ms][2]), w.x, racc[ms][1]);
                    racc[ms][1] = fmaf(ex2f(acc[nb4][ms][3]), w.y, racc[ms][1]);
                }
            }
        }
    }

    // Partial write (deterministic slots)
    #pragma unroll
    for (int ms = 0; ms < 2; ms++)
        #pragma unroll
        for (int h = 0; h < 2; h++) {
            float v = racc[ms][h];
            v += __shfl_xor_sync(0xFFFFFFFFu, v, 1);
            v += __shfl_xor_sync(0xFFFFFFFFu, v, 2);
            if (tg == 0) {
                int b = m0 + warp_m * 32 + ms * 16 + h * 8 + g;
                g_partial[(ns * BB + b) * 2 + warp_n] = v;
            }
        }

    // Fused reduce: last of the 8 CTAs sharing this b-tile finishes it.
    __threadfence();
    __syncthreads();
    if (tid == 0) s_flag = (atomicAdd(&g_arr[bt], 1) == NSPLITS - 1);
    __syncthreads();
    if (s_flag) {
        __threadfence();
        if (tid < BT) {
            int b = m0 + tid;
            float s = 0.0f;
            #pragma unroll
            for (int n2 = 0; n2 < NSPLITS; n2++) {
                s += g_partial[(n2 * BB + b) * 2 + 0];
                s += g_partial[(n2 * BB + b) * 2 + 1];
            }
            out[b] = fmaf(g_ex[b], s, __ldg(bias));
        }
        if (tid == 0) g_arr[bt] = 0;   // reset for next graph replay
    }
}

// ============================================================================
// Entry
// ============================================================================
extern "C" void kernel_launch(void* const* d_in, const int* in_sizes, int n_in,
                              void* d_out, int out_size) {
    const float* x     = (const float*)d_in[0];   // [2048, 128]
    const float* train = (const float*)d_in[1];   // [32768, 128]
    const float* gamma = (const float*)d_in[2];   // [1]
    const float* W     = (const float*)d_in[3];   // [1, 32768]
    const float* bias  = (const float*)d_in[4];   // [1]
    float* out = (float*)d_out;                   // [2048, 1]

    cudaFuncSetAttribute(rbf_main_kernel,
                         cudaFuncAttributeMaxDynamicSharedMemorySize, SMEM_TOTAL);

    prep_x_kernel<<<(BB * 32) / THREADS, THREADS>>>(x, gamma);
    prep_t_kernel<<<(NN * 32) / THREADS, THREADS>>>(train, gamma, W);
    rbf_main_kernel<<<dim3(NSPLITS, BTILES), THREADS, SMEM_TOTAL>>>(bias, out);
}